// round 15
// baseline (speedup 1.0000x reference)
#include <cuda_runtime.h>
#include <cstdint>

#define N_CTRL   256
#define KLEN     260     // N_CTRL + DEGREE + 1
#define OUT_X    1024
#define OUT_Y    1024
#define DEG      3
#define EPS_     1e-05f

#define GRID_B   128
#define BLOCK_T  512

// ---------------- device scratch (no allocations allowed) ----------------
__device__ float4 g_bx[OUT_X];
__device__ float4 g_by[OUT_Y];
__device__ int4   g_ix[OUT_X];
__device__ int4   g_iy[OUT_Y];
__device__ float4 g_cp4[N_CTRL * N_CTRL];        // 1 MB packed control points
__device__ float4 g_T[N_CTRL * OUT_Y];           // 4 MB intermediate T[i][f]

// ---- software grid barrier state (self-resetting across graph replays) ----
__device__ unsigned g_bar_count = 0;
__device__ volatile unsigned g_bar_gen = 0;

__device__ __forceinline__ void grid_barrier() {
    __syncthreads();
    if (threadIdx.x == 0) {
        __threadfence();
        unsigned gen = g_bar_gen;
        if (atomicInc(&g_bar_count, GRID_B - 1) == GRID_B - 1) {
            g_bar_gen = gen + 1;          // release: count auto-wrapped to 0
        } else {
            while (g_bar_gen == gen) { __nanosleep(64); }
        }
    }
    __syncthreads();
}

__device__ __forceinline__ int imod(int a, int m) {
    int r = a % m;
    return r < 0 ? r + m : r;
}

// ---------------- single fused kernel -------------------------------------
__global__ void __launch_bounds__(BLOCK_T, 1)
nurbs_fused_kernel(const float* __restrict__ cp,
                   const float* __restrict__ kx_in,
                   const float* __restrict__ ky_in,
                   float* __restrict__ out) {
    const int b = blockIdx.x;
    const int t = threadIdx.x;

    // =================== phase 0: basis (blocks 0,1) + pack (2..127) =====
    if (b < 2) {
        __shared__ float kn[KLEN];
        __shared__ float wtot[16];
        const float* in = (b == 0) ? kx_in : ky_in;

        int lane = t & 31;
        int w    = t >> 5;

        // parallel load (one coalesced burst) + clamp
        float v = 0.f;
        if (t < KLEN) {
            v = in[t];
            if (v < 0.f) v = 1e-4f;     // jnp.where(k < 0, 0.0001, k)
        }

        // level 1: per-warp inclusive scan (warps 0..8 cover 260)
        float vs = v;
        if (w < 9) {
            #pragma unroll
            for (int off = 1; off < 32; off <<= 1) {
                float n = __shfl_up_sync(0xffffffffu, vs, off);
                if (lane >= off) vs += n;
            }
            if (lane == 31) wtot[w] = vs;
        }
        __syncthreads();

        // level 2: warp 0 scans the 9 warp totals
        if (t < 32) {
            float tv = (t < 9) ? wtot[t] : 0.f;
            #pragma unroll
            for (int off = 1; off < 16; off <<= 1) {
                float n = __shfl_up_sync(0xffffffffu, tv, off);
                if (lane >= off) tv += n;
            }
            if (t < 9) wtot[t] = tv;    // inclusive totals
        }
        __syncthreads();

        if (t < KLEN) {
            float pre = (w > 0) ? wtot[w - 1] : 0.f;
            kn[t] = vs + pre;
        }
        __syncthreads();

        // normalize in place
        float k0  = kn[0];
        float inv = __fdividef(1.f, kn[KLEN - 1] - k0);
        __syncthreads();
        if (t < KLEN) kn[t] = (kn[t] - k0) * inv;
        __syncthreads();

        // per-sample span + Cox-de Boor basis: 512 threads x 2 samples
        const float step = (1.0f - 2.0f * EPS_) / 1023.0f;
        #pragma unroll
        for (int rep = 0; rep < 2; rep++) {
            int e = t + rep * BLOCK_T;           // 0..1023
            float u = EPS_ + (float)e * step;

            int lo = 0, hi = KLEN;
            while (lo < hi) {
                int mid = (lo + hi) >> 1;
                if (kn[mid] <= u) lo = mid + 1; else hi = mid;
            }
            int span = lo - 1;
            if (u == kn[N_CTRL]) span = N_CTRL - 1;

            float left[DEG + 1], right[DEG + 1], N[DEG + 1];
            N[0] = 1.f;
            #pragma unroll
            for (int j = 1; j <= DEG; j++) {
                left[j]  = u - kn[imod(span + 1 - j, KLEN)];
                right[j] = kn[imod(span + j, KLEN)] - u;
                float saved = 0.f;
                #pragma unroll
                for (int r = 0; r < j; r++) {
                    float temp = __fdividef(N[r], right[r + 1] + left[j - r]);
                    N[r]  = saved + right[r + 1] * temp;
                    saved = left[j - r] * temp;
                }
                N[j] = saved;
            }

            float4 bb = make_float4(N[0], N[1], N[2], N[3]);
            int4 ii;
            ii.x = imod(span - DEG + 0, N_CTRL);
            ii.y = imod(span - DEG + 1, N_CTRL);
            ii.z = imod(span - DEG + 2, N_CTRL);
            ii.w = imod(span - DEG + 3, N_CTRL);

            if (b == 0) { g_bx[e] = bb; g_ix[e] = ii; }
            else        { g_by[e] = bb; g_iy[e] = ii; }
        }
    } else {
        // pack control points: 126 blocks cover 65536 float4s
        for (int idx = (b - 2) * BLOCK_T + t; idx < N_CTRL * N_CTRL;
             idx += 126 * BLOCK_T) {
            const float* p = cp + (size_t)idx * 3;
            g_cp4[idx] = make_float4(p[0], p[1], p[2], 0.f);
        }
    }

    grid_barrier();

    // =================== phase 1: T[i][f] = sum_r by[f][r]*cp4[i][iy_r] ===
    {
        int gt  = b * BLOCK_T + t;          // 0..65535
        int f   = gt & (OUT_Y - 1);
        int i0  = (gt >> 10) * 4;           // 64 groups * 4 = 256 rows
        float4 by = g_by[f];
        int4   iy = g_iy[f];
        #pragma unroll
        for (int k = 0; k < 4; k++) {
            int i = i0 + k;
            const float4* row = g_cp4 + i * N_CTRL;
            float4 a  = row[iy.x];
            float4 bq = row[iy.y];
            float4 c  = row[iy.z];
            float4 d  = row[iy.w];
            float4 tt;
            tt.x = by.x * a.x + by.y * bq.x + by.z * c.x + by.w * d.x;
            tt.y = by.x * a.y + by.y * bq.y + by.z * c.y + by.w * d.y;
            tt.z = by.x * a.z + by.y * bq.z + by.z * c.z + by.w * d.z;
            tt.w = 0.f;
            g_T[i * OUT_Y + f] = tt;
        }
    }

    grid_barrier();

    // =================== phase 2: out[e][f] = sum_l bx[e][l]*T[ix_l][f] ===
    {
        int e0  = b * 8 + (t >> 8) * 4;     // block covers 8 e, half-block 4
        int f0  = (t & 255) * 4;

        #pragma unroll
        for (int ei = 0; ei < 4; ei++) {
            int e = e0 + ei;
            float4 bx = g_bx[e];
            int4   ix = g_ix[e];

            float bw[4] = {bx.x, bx.y, bx.z, bx.w};
            int   ir[4] = {ix.x, ix.y, ix.z, ix.w};

            float4 a0 = make_float4(0, 0, 0, 0);
            float4 a1 = make_float4(0, 0, 0, 0);
            float4 a2 = make_float4(0, 0, 0, 0);
            float4 a3 = make_float4(0, 0, 0, 0);

            #pragma unroll
            for (int l = 0; l < 4; l++) {
                const float4* r = g_T + (size_t)ir[l] * OUT_Y + f0;
                float w = bw[l];
                float4 v0 = r[0], v1 = r[1], v2 = r[2], v3 = r[3];
                a0.x += w * v0.x; a0.y += w * v0.y; a0.z += w * v0.z;
                a1.x += w * v1.x; a1.y += w * v1.y; a1.z += w * v1.z;
                a2.x += w * v2.x; a2.y += w * v2.y; a2.z += w * v2.z;
                a3.x += w * v3.x; a3.y += w * v3.y; a3.z += w * v3.z;
            }

            float* o = out + ((size_t)e * OUT_Y + f0) * 3;
            float4 o0 = make_float4(a0.x, a0.y, a0.z, a1.x);
            float4 o1 = make_float4(a1.y, a1.z, a2.x, a2.y);
            float4 o2 = make_float4(a2.z, a3.x, a3.y, a3.z);
            reinterpret_cast<float4*>(o)[0] = o0;
            reinterpret_cast<float4*>(o)[1] = o1;
            reinterpret_cast<float4*>(o)[2] = o2;
        }
    }
}

// ---------------------------- launch --------------------------------------
extern "C" void kernel_launch(void* const* d_in, const int* in_sizes, int n_in,
                              void* d_out, int out_size) {
    const float* cp = (const float*)d_in[0];
    const float* kx = (const float*)d_in[1];
    const float* ky = (const float*)d_in[2];
    float* out = (float*)d_out;

    nurbs_fused_kernel<<<GRID_B, BLOCK_T>>>(cp, kx, ky, out);
}